// round 12
// baseline (speedup 1.0000x reference)
#include <cuda_runtime.h>

// Problem constants
#define NB   32
#define NT   4096
#define NF   1024     // F_IN
#define NH   16
#define NDEP 64
#define NDM  1024     // D
#define KS   8        // pass1 k-split factor (128 k per split)
#define TC2  32       // pass2 t-chunks (128 t each)
#define APS  18       // attnP row stride (ull), even => ulonglong2-aligned

typedef unsigned long long ull;

// ---------------- scratch (device globals; no allocation) ----------------
__device__ float g_qpart[32 * NB * NDM];
__device__ float g_q[NB * NDM];
__device__ ull   g_p2[NB * 512 * NH];            // (p[2P][h], p[2P+1][h]) pairs
__device__ float g_Lp[KS * NB * NH * NT];        // logit k-split partials (64MB)
__device__ float g_attn[NB * NH * NT];           // attn weights [b][h][t]
__device__ float g_wp[NB * TC2 * NH * NF];       // pass2 t-chunk partials (64MB)
__device__ float g_op[16 * NB * NDM];
__device__ float g_out[NB * NDM];
__device__ float g_fpart[32 * NB * NDM];

// ---------------- helpers ----------------
__device__ __forceinline__ ull pk2(float lo, float hi) {
    ull r;
    asm("mov.b64 %0, {%1, %2};" : "=l"(r) : "f"(lo), "f"(hi));
    return r;
}
__device__ __forceinline__ ull ffma2(ull a, ull b, ull c) {
    ull d;
    asm("fma.rn.f32x2 %0, %1, %2, %3;" : "=l"(d) : "l"(a), "l"(b), "l"(c));
    return d;
}
__device__ __forceinline__ void upk2(ull v, float& lo, float& hi) {
    asm("mov.b64 {%0, %1}, %2;" : "=f"(lo), "=f"(hi) : "l"(v));
}
__device__ __forceinline__ void cpa16(unsigned dst, const void* src) {
    asm volatile("cp.async.cg.shared.global [%0], [%1], 16;" :: "r"(dst), "l"(src));
}
__device__ __forceinline__ void cpacommit() {
    asm volatile("cp.async.commit_group;" ::: "memory");
}
__device__ __forceinline__ void cpawait0() {
    asm volatile("cp.async.wait_group 0;" ::: "memory");
}

// ---------------- 32-batch GEMV, 32-way k-split partials ----------
__global__ void gemv_part_kernel(const float* __restrict__ X,
                                 const float* __restrict__ W,
                                 float* __restrict__ part) {
    __shared__ float xs[32][32];
    const int jt = blockIdx.x, kc = blockIdx.y, tid = threadIdx.x;
    for (int i = tid; i < 32 * 32; i += 128) {
        int bb = i >> 5, kl = i & 31;
        xs[bb][kl] = X[bb * NDM + kc * 32 + kl];
    }
    __syncthreads();
    const int j = jt * 128 + tid;
    float acc[32];
#pragma unroll
    for (int bb = 0; bb < 32; bb++) acc[bb] = 0.f;
    for (int kl = 0; kl < 32; kl++) {
        float wv = W[(kc * 32 + kl) * NDM + j];
#pragma unroll
        for (int bb = 0; bb < 32; bb++) acc[bb] += xs[bb][kl] * wv;
    }
#pragma unroll
    for (int bb = 0; bb < 32; bb++) part[(kc * 32 + bb) * NDM + j] = acc[bb];
}

__global__ void combine32_kernel(const float* __restrict__ part,
                                 const float* __restrict__ bias,
                                 float* __restrict__ out) {
    int i = blockIdx.x * 256 + threadIdx.x;
    float s = bias[i & (NDM - 1)];
#pragma unroll
    for (int c = 0; c < 32; c++) s += part[c * (32 * NDM) + i];
    out[i] = s;
}

__global__ void combine16_kernel(const float* __restrict__ part,
                                 const float* __restrict__ bias,
                                 float* __restrict__ out) {
    int i = blockIdx.x * 256 + threadIdx.x;
    float s = bias[i & (NDM - 1)];
#pragma unroll
    for (int c = 0; c < 16; c++) s += part[c * (32 * NDM) + i];
    out[i] = s;
}

// ---------------- p2[b][P][h] = (1/8)*(sum_d Wv[2P][..]q, sum_d Wv[2P+1][..]q)
__global__ void pcalc_kernel(const float* __restrict__ Wv) {
    __shared__ float qs[8][NDM];
    const int ft = blockIdx.x, bg = blockIdx.y, tid = threadIdx.x;
    for (int i = tid; i < 8 * NDM; i += 256)
        qs[i >> 10][i & 1023] = g_q[(bg * 8 + (i >> 10)) * NDM + (i & 1023)];
    __syncthreads();
    const int h = tid >> 4, fl = tid & 15;
    const int f = ft * 16 + fl;
    float acc[8];
#pragma unroll
    for (int bb = 0; bb < 8; bb++) acc[bb] = 0.f;
    for (int d = 0; d < NDEP; d++) {
        float wv = Wv[f * NDM + h * NDEP + d];
#pragma unroll
        for (int bb = 0; bb < 8; bb++) acc[bb] += wv * qs[bb][h * NDEP + d];
    }
    float* p2f = (float*)g_p2;
#pragma unroll
    for (int bb = 0; bb < 8; bb++) {
        int b = bg * 8 + bb;
        p2f[(((b * 512) + (f >> 1)) * NH + h) * 2 + (f & 1)] = acc[bb] * 0.125f;
    }
}

// ---------------- pass1: Lp[kz][b][h][t] = sum_{k in 128-slice kz} F[t][k]*p[k][h]
// grid (8 t-tiles of 512, 32 b, 8 kz), 128 threads; 3 blocks/SM (72KB smem)
__global__ __launch_bounds__(128) void pass1_kernel(const float* __restrict__ F) {
    extern __shared__ __align__(16) char sm1[];
    float4* Fs = (float4*)sm1;                        // 2 * 2048 float4
    ull* p2s = (ull*)(sm1 + 2 * 2048 * 16);           // 1024 ull = 8KB
    const unsigned fs_base = (unsigned)__cvta_generic_to_shared(Fs);
    const unsigned p2_base = (unsigned)__cvta_generic_to_shared(p2s);

    const int b = blockIdx.y, kz = blockIdx.z;
    const int tbase = blockIdx.x * 512;
    const int tid = threadIdx.x;
    const int hg = tid >> 6, h0 = hg * 8, rg = tid & 63;
    const int r0 = rg * 4;
    const int keyc = rg & 7;

    {
        const float4* src = (const float4*)(g_p2 + (b * 512 + kz * 64) * NH);
#pragma unroll
        for (int it = 0; it < 4; it++) {
            int i = tid + 128 * it;
            cpa16(p2_base + i * 16, src + i);
        }
        const float* base = F + (b * NT + tbase) * NF + kz * 128;
#pragma unroll
        for (int it = 0; it < 16; it++) {
            int i = tid + 128 * it;
            int row = i >> 3, c = i & 7;
            cpa16(fs_base + (row * 8 + (c ^ ((row >> 2) & 7))) * 16,
                  base + row * NF + c * 4);
        }
        cpacommit();
    }

    ull acc[4][8];
#pragma unroll
    for (int r = 0; r < 4; r++)
#pragma unroll
        for (int hh = 0; hh < 8; hh++) acc[r][hh] = 0ull;

    for (int s = 0; s < 8; s++) {
        cpawait0();
        __syncthreads();
        if (s < 7) {
            int sn = s + 1;
            int half = sn >> 2, kc = sn & 3;
            const float* base = F + (b * NT + tbase + half * 256) * NF
                              + kz * 128 + kc * 32;
            unsigned dstb = fs_base + (sn & 1) * 2048 * 16;
#pragma unroll
            for (int it = 0; it < 16; it++) {
                int i = tid + 128 * it;
                int row = i >> 3, c = i & 7;
                cpa16(dstb + (row * 8 + (c ^ ((row >> 2) & 7))) * 16,
                      base + row * NF + c * 4);
            }
            cpacommit();
        }
        const float4* buf = Fs + (s & 1) * 2048;
        const int kc = s & 3;
#pragma unroll
        for (int c = 0; c < 8; c++) {
            ull pp0[8], pp1[8];
            {
                const ulonglong2* q0 = (const ulonglong2*)(p2s + (kc * 16 + c * 2) * NH + h0);
                const ulonglong2* q1 = (const ulonglong2*)(p2s + (kc * 16 + c * 2 + 1) * NH + h0);
#pragma unroll
                for (int q = 0; q < 4; q++) {
                    ulonglong2 a = q0[q]; pp0[2 * q] = a.x; pp0[2 * q + 1] = a.y;
                    ulonglong2 bq = q1[q]; pp1[2 * q] = bq.x; pp1[2 * q + 1] = bq.y;
                }
            }
#pragma unroll
            for (int r = 0; r < 4; r++) {
                int row = r0 + r;
                ulonglong2 u = *(const ulonglong2*)(buf + row * 8 + (c ^ keyc));
#pragma unroll
                for (int hh = 0; hh < 8; hh++) {
                    acc[r][hh] = ffma2(u.x, pp0[hh], acc[r][hh]);
                    acc[r][hh] = ffma2(u.y, pp1[hh], acc[r][hh]);
                }
            }
        }
        if (kc == 3) {
            int half = s >> 2;
#pragma unroll
            for (int hh = 0; hh < 8; hh++) {
                float4 o;
                float lo, hi;
                upk2(acc[0][hh], lo, hi); o.x = lo + hi;
                upk2(acc[1][hh], lo, hi); o.y = lo + hi;
                upk2(acc[2][hh], lo, hi); o.z = lo + hi;
                upk2(acc[3][hh], lo, hi); o.w = lo + hi;
                *(float4*)(g_Lp + ((kz * NB + b) * NH + h0 + hh) * NT
                           + tbase + half * 256 + r0) = o;
            }
#pragma unroll
            for (int r = 0; r < 4; r++)
#pragma unroll
                for (int hh = 0; hh < 8; hh++) acc[r][hh] = 0ull;
        }
    }
}

// ---------------- softmax: sum 8 k-split partials, softmax, write g_attn
__global__ void softmax_kernel() {
    __shared__ float red[8];
    const int bh = blockIdx.x, tid = threadIdx.x;
    const int wid = tid >> 5, lid = tid & 31;
    const float4* L0 = (const float4*)(g_Lp + bh * NT);
    const int STRIDE4 = NB * NH * NT / 4;
    float4* Ao = (float4*)(g_attn + bh * NT);

    float4 v[4];
    float lmax = -1e30f;
#pragma unroll
    for (int j = 0; j < 4; j++) {
        int i = tid + 256 * j;
        float4 x = L0[i];
#pragma unroll
        for (int k = 1; k < KS; k++) {
            float4 a = L0[k * STRIDE4 + i];
            x.x += a.x; x.y += a.y; x.z += a.z; x.w += a.w;
        }
        v[j] = x;
        lmax = fmaxf(lmax, fmaxf(fmaxf(x.x, x.y), fmaxf(x.z, x.w)));
    }
#pragma unroll
    for (int o = 16; o > 0; o >>= 1)
        lmax = fmaxf(lmax, __shfl_xor_sync(0xffffffffu, lmax, o));
    if (lid == 0) red[wid] = lmax;
    __syncthreads();
    {
        float t = red[lid & 7];
#pragma unroll
        for (int o = 4; o > 0; o >>= 1)
            t = fmaxf(t, __shfl_xor_sync(0xffffffffu, t, o));
        lmax = t;
    }
    float lsum = 0.f;
#pragma unroll
    for (int j = 0; j < 4; j++) {
        float4 x = v[j];
        x.x = __expf(x.x - lmax); x.y = __expf(x.y - lmax);
        x.z = __expf(x.z - lmax); x.w = __expf(x.w - lmax);
        v[j] = x;
        lsum += x.x + x.y + x.z + x.w;
    }
#pragma unroll
    for (int o = 16; o > 0; o >>= 1)
        lsum += __shfl_xor_sync(0xffffffffu, lsum, o);
    __syncthreads();
    if (lid == 0) red[wid] = lsum;
    __syncthreads();
    {
        float t = red[lid & 7];
#pragma unroll
        for (int o = 4; o > 0; o >>= 1)
            t += __shfl_xor_sync(0xffffffffu, t, o);
        lsum = t;
    }
    float inv = 1.f / lsum;
#pragma unroll
    for (int j = 0; j < 4; j++) {
        float4 x = v[j];
        x.x *= inv; x.y *= inv; x.z *= inv; x.w *= inv;
        Ao[tid + 256 * j] = x;
    }
}

// ---------------- pass2: wp[b][c][h][f] = sum_{t in 128-chunk} A[h][t]*F[t][f]
// grid (32 t-chunks, 32 b reversed), 256 threads, FORCED 2 blocks/SM
__global__ __launch_bounds__(256, 2) void pass2_kernel(const float* __restrict__ F) {
    extern __shared__ __align__(16) char sm2[];
    float4* Fs = (float4*)sm2;                        // 2 * 2048 float4 = 64 KB
    ull* attnP = (ull*)(sm2 + 2 * 2048 * 16);         // 128 * APS ull = 18 KB
    const unsigned fs_base = (unsigned)__cvta_generic_to_shared(Fs);

    const int b = (NB - 1) - blockIdx.y;
    const int cblk = blockIdx.x;
    const int tb = cblk * 128;
    const int tid = threadIdx.x;
    const int hg = tid >> 7, h0 = hg * 8, fg = tid & 127;

    {
        const float* base = F + (b * NT + tb) * NF;
#pragma unroll
        for (int it = 0; it < 8; it++) {
            int i = tid + 256 * it;
            int row = i >> 8, c = i & 255;
            cpa16(fs_base + (row * 256 + c) * 16, base + row * NF + c * 4);
        }
        cpacommit();
        // attn pair table: coalesced LDG from [b][h][t], pk2, padded STS
#pragma unroll
        for (int it = 0; it < 8; it++) {
            int i = tid + 256 * it;                   // 0..2047
            int h = i >> 7, t = i & 127;
            float a = g_attn[(b * NH + h) * NT + tb + t];
            attnP[t * APS + h] = pk2(a, a);
        }
    }

    ull acc[8][4];
#pragma unroll
    for (int hh = 0; hh < 8; hh++)
#pragma unroll
        for (int r = 0; r < 4; r++) acc[hh][r] = 0ull;

    for (int s = 0; s < 16; s++) {
        cpawait0();
        __syncthreads();
        if (s < 15) {
            int t0 = tb + (s + 1) * 8;
            const float* base = F + (b * NT + t0) * NF;
            unsigned dstb = fs_base + ((s + 1) & 1) * 2048 * 16;
#pragma unroll
            for (int it = 0; it < 8; it++) {
                int i = tid + 256 * it;
                int row = i >> 8, c = i & 255;
                cpa16(dstb + (row * 256 + c) * 16, base + row * NF + c * 4);
            }
            cpacommit();
        }
        const float4* buf = Fs + (s & 1) * 2048;
#pragma unroll
        for (int kk = 0; kk < 8; kk++) {
            ull pp[8];
            {
                const ulonglong2* q =
                    (const ulonglong2*)(attnP + (s * 8 + kk) * APS + h0);
#pragma unroll
                for (int qi = 0; qi < 4; qi++) {
                    ulonglong2 a = q[qi];
                    pp[2 * qi] = a.x; pp[2 * qi + 1] = a.y;
                }
            }
            ulonglong2 ua = *(const ulonglong2*)(buf + kk * 256 + fg);
            ulonglong2 ub = *(const ulonglong2*)(buf + kk * 256 + 128 + fg);
#pragma unroll
            for (int hh = 0; hh < 8; hh++) {
                acc[hh][0] = ffma2(ua.x, pp[hh], acc[hh][0]);
                acc[hh][1] = ffma2(ua.y, pp[hh], acc[hh][1]);
                acc[hh][2] = ffma2(ub.x, pp[hh], acc[hh][2]);
                acc[hh][3] = ffma2(ub.y, pp[hh], acc[hh][3]);
            }
        }
    }
#pragma unroll
    for (int hh = 0; hh < 8; hh++) {
        float o0, o1, o2, o3;
        float* wpp = g_wp + ((b * TC2 + cblk) * NH + h0 + hh) * NF;
        upk2(acc[hh][0], o0, o1); upk2(acc[hh][1], o2, o3);
        *(float4*)(wpp + fg * 4) = make_float4(o0, o1, o2, o3);
        upk2(acc[hh][2], o0, o1); upk2(acc[hh][3], o2, o3);
        *(float4*)(wpp + 512 + fg * 4) = make_float4(o0, o1, o2, o3);
    }
}

// op[fc][b][j] = sum_{f in 64-chunk fc} (sum_c wp[b][c][..][f]) * Wv[f][j]
__global__ void outpart_kernel(const float* __restrict__ Wv) {
    __shared__ float ws[16][2][64];
    const int jt = blockIdx.x, fc = blockIdx.y, bg = blockIdx.z;
    const int tid = threadIdx.x;
    for (int i = tid; i < 16 * 2 * 64; i += 128) {
        int bb = i >> 7, hl = (i >> 6) & 1, fl = i & 63;
        int bglob = bg * 16 + bb;
        float s = 0.f;
#pragma unroll
        for (int c = 0; c < TC2; c++)
            s += g_wp[((bglob * TC2 + c) * NH + jt * 2 + hl) * NF + fc * 64 + fl];
        ws[bb][hl][fl] = s;
    }
    __syncthreads();
    const int j = jt * 128 + tid;
    const int hl = tid >> 6;
    float acc[16];
#pragma unroll
    for (int bb = 0; bb < 16; bb++) acc[bb] = 0.f;
    for (int fl = 0; fl < 64; fl++) {
        float wvv = Wv[(fc * 64 + fl) * NDM + j];
#pragma unroll
        for (int bb = 0; bb < 16; bb++) acc[bb] += ws[bb][hl][fl] * wvv;
    }
#pragma unroll
    for (int bb = 0; bb < 16; bb++)
        g_op[(fc * 32 + bg * 16 + bb) * NDM + j] = acc[bb];
}

// ---------------- host launcher ----------------
extern "C" void kernel_launch(void* const* d_in, const int* in_sizes, int n_in,
                              void* d_out, int out_size) {
    const float* features = (const float*)d_in[0];
    const float* state    = (const float*)d_in[1];
    const float* Wq       = (const float*)d_in[2];
    const float* bq       = (const float*)d_in[3];
    const float* Wv       = (const float*)d_in[4];
    const float* bv       = (const float*)d_in[5];
    const float* Wd       = (const float*)d_in[6];
    const float* bd       = (const float*)d_in[7];
    float* out = (float*)d_out;

    void *p_qpart, *p_op, *p_out, *p_fpart, *p_q;
    cudaGetSymbolAddress(&p_qpart, g_qpart);
    cudaGetSymbolAddress(&p_op, g_op);
    cudaGetSymbolAddress(&p_out, g_out);
    cudaGetSymbolAddress(&p_fpart, g_fpart);
    cudaGetSymbolAddress(&p_q, g_q);

    const int SM1 = 2 * 2048 * 16 + 1024 * 8;        // 73728 -> 3 blocks/SM
    const int SM2 = 2 * 2048 * 16 + 128 * APS * 8;   // 83968 -> 2 blocks/SM
    static int cfg_done = 0;
    if (!cfg_done) {
        cudaFuncSetAttribute(pass1_kernel,
            cudaFuncAttributeMaxDynamicSharedMemorySize, SM1);
        cudaFuncSetAttribute(pass2_kernel,
            cudaFuncAttributeMaxDynamicSharedMemorySize, SM2);
        cfg_done = 1;
    }

    // q = state @ Wq + bq
    gemv_part_kernel<<<dim3(8, 32), 128>>>(state, Wq, (float*)p_qpart);
    combine32_kernel<<<128, 256>>>((const float*)p_qpart, bq, (float*)p_q);
    // p2 pairs
    pcalc_kernel<<<dim3(64, 4), 256>>>(Wv);
    // logit partials (k-split x8, 3 blocks/SM)
    pass1_kernel<<<dim3(8, 32, KS), 128, SM1>>>(features);
    // softmax -> attn [b][h][t]
    softmax_kernel<<<NB * NH, 256>>>();
    // w partials = attn @ features (forced 2 blocks/SM)
    pass2_kernel<<<dim3(TC2, 32), 256, SM2>>>(features);
    // out = (sum_c wp) @ Wv + bv
    outpart_kernel<<<dim3(8, 16, 2), 128>>>(Wv);
    combine16_kernel<<<128, 256>>>((const float*)p_op, bv, (float*)p_out);
    // final = out @ Wd + bd
    gemv_part_kernel<<<dim3(8, 32), 128>>>((const float*)p_out, Wd, (float*)p_fpart);
    combine32_kernel<<<128, 256>>>((const float*)p_fpart, bd, out);
    (void)in_sizes; (void)n_in; (void)out_size;
}

// round 13
// speedup vs baseline: 1.0186x; 1.0186x over previous
#include <cuda_runtime.h>

// Problem constants
#define NB   32
#define NT   4096
#define NF   1024     // F_IN
#define NH   16
#define NDEP 64
#define NDM  1024     // D
#define KS   8        // pass1 k-split factor (128 k per split)
#define TC2  16       // pass2 t-chunks (256 t each)
#define APS  18       // attnP row stride (ull), even => ulonglong2-aligned

typedef unsigned long long ull;

// ---------------- scratch (device globals; no allocation) ----------------
__device__ float g_qpart[32 * NB * NDM];
__device__ float g_q[NB * NDM];
__device__ ull   g_p2[NB * 512 * NH];            // (p[2P][h], p[2P+1][h]) pairs
__device__ float g_Lp[KS * NB * NH * NT];        // logit k-split partials (64MB)
__device__ float g_attn[NB * NH * NT];           // attn weights [b][h][t]
__device__ float g_wp[NB * TC2 * NH * NF];       // pass2 t-chunk partials (32MB)
__device__ float g_op[16 * NB * NDM];
__device__ float g_fpart[32 * NB * NDM];

// ---------------- helpers ----------------
__device__ __forceinline__ ull pk2(float lo, float hi) {
    ull r;
    asm("mov.b64 %0, {%1, %2};" : "=l"(r) : "f"(lo), "f"(hi));
    return r;
}
__device__ __forceinline__ ull ffma2(ull a, ull b, ull c) {
    ull d;
    asm("fma.rn.f32x2 %0, %1, %2, %3;" : "=l"(d) : "l"(a), "l"(b), "l"(c));
    return d;
}
__device__ __forceinline__ void upk2(ull v, float& lo, float& hi) {
    asm("mov.b64 {%0, %1}, %2;" : "=f"(lo), "=f"(hi) : "l"(v));
}
__device__ __forceinline__ void cpa16(unsigned dst, const void* src) {
    asm volatile("cp.async.cg.shared.global [%0], [%1], 16;" :: "r"(dst), "l"(src));
}
__device__ __forceinline__ void cpacommit() {
    asm volatile("cp.async.commit_group;" ::: "memory");
}
__device__ __forceinline__ void cpawait0() {
    asm volatile("cp.async.wait_group 0;" ::: "memory");
}

// ---------------- 32-batch GEMV, 32-way k-split partials ----------
__global__ void gemv_part_kernel(const float* __restrict__ X,
                                 const float* __restrict__ W,
                                 float* __restrict__ part) {
    __shared__ float xs[32][32];
    const int jt = blockIdx.x, kc = blockIdx.y, tid = threadIdx.x;
    for (int i = tid; i < 32 * 32; i += 128) {
        int bb = i >> 5, kl = i & 31;
        xs[bb][kl] = X[bb * NDM + kc * 32 + kl];
    }
    __syncthreads();
    const int j = jt * 128 + tid;
    float acc[32];
#pragma unroll
    for (int bb = 0; bb < 32; bb++) acc[bb] = 0.f;
    for (int kl = 0; kl < 32; kl++) {
        float wv = W[(kc * 32 + kl) * NDM + j];
#pragma unroll
        for (int bb = 0; bb < 32; bb++) acc[bb] += xs[bb][kl] * wv;
    }
#pragma unroll
    for (int bb = 0; bb < 32; bb++) part[(kc * 32 + bb) * NDM + j] = acc[bb];
}

// final GEMV: X built inline as bv + sum_fc op[fc]
__global__ void gemv_final_kernel(const float* __restrict__ W,
                                  const float* __restrict__ bv,
                                  float* __restrict__ part) {
    __shared__ float xs[32][32];
    const int jt = blockIdx.x, kc = blockIdx.y, tid = threadIdx.x;
    for (int i = tid; i < 32 * 32; i += 128) {
        int bb = i >> 5, kl = i & 31;
        int col = kc * 32 + kl;
        float s = bv[col];
#pragma unroll
        for (int fc = 0; fc < 16; fc++)
            s += g_op[fc * (32 * NDM) + bb * NDM + col];
        xs[bb][kl] = s;
    }
    __syncthreads();
    const int j = jt * 128 + tid;
    float acc[32];
#pragma unroll
    for (int bb = 0; bb < 32; bb++) acc[bb] = 0.f;
    for (int kl = 0; kl < 32; kl++) {
        float wv = W[(kc * 32 + kl) * NDM + j];
#pragma unroll
        for (int bb = 0; bb < 32; bb++) acc[bb] += xs[bb][kl] * wv;
    }
#pragma unroll
    for (int bb = 0; bb < 32; bb++) part[(kc * 32 + bb) * NDM + j] = acc[bb];
}

__global__ void combine32_kernel(const float* __restrict__ part,
                                 const float* __restrict__ bias,
                                 float* __restrict__ out) {
    int i = blockIdx.x * 256 + threadIdx.x;
    float s = bias[i & (NDM - 1)];
#pragma unroll
    for (int c = 0; c < 32; c++) s += part[c * (32 * NDM) + i];
    out[i] = s;
}

// ---------------- p2[b][P][h] = (1/8)*(sum_d Wv[2P][..]q, sum_d Wv[2P+1][..]q)
__global__ void pcalc_kernel(const float* __restrict__ Wv) {
    __shared__ float qs[8][NDM];
    const int ft = blockIdx.x, bg = blockIdx.y, tid = threadIdx.x;
    for (int i = tid; i < 8 * NDM; i += 256)
        qs[i >> 10][i & 1023] = g_q[(bg * 8 + (i >> 10)) * NDM + (i & 1023)];
    __syncthreads();
    const int h = tid >> 4, fl = tid & 15;
    const int f = ft * 16 + fl;
    float acc[8];
#pragma unroll
    for (int bb = 0; bb < 8; bb++) acc[bb] = 0.f;
    for (int d = 0; d < NDEP; d++) {
        float wv = Wv[f * NDM + h * NDEP + d];
#pragma unroll
        for (int bb = 0; bb < 8; bb++) acc[bb] += wv * qs[bb][h * NDEP + d];
    }
    float* p2f = (float*)g_p2;
#pragma unroll
    for (int bb = 0; bb < 8; bb++) {
        int b = bg * 8 + bb;
        p2f[(((b * 512) + (f >> 1)) * NH + h) * 2 + (f & 1)] = acc[bb] * 0.125f;
    }
}

// ---------------- pass1: Lp[kz][b][h][t] = sum_{k in 128-slice kz} F[t][k]*p[k][h]
// grid (8 t-tiles of 512, 32 b, 8 kz), 128 threads; 3 blocks/SM (72KB smem)
__global__ __launch_bounds__(128) void pass1_kernel(const float* __restrict__ F) {
    extern __shared__ __align__(16) char sm1[];
    float4* Fs = (float4*)sm1;                        // 2 * 2048 float4
    ull* p2s = (ull*)(sm1 + 2 * 2048 * 16);           // 1024 ull = 8KB
    const unsigned fs_base = (unsigned)__cvta_generic_to_shared(Fs);
    const unsigned p2_base = (unsigned)__cvta_generic_to_shared(p2s);

    const int b = blockIdx.y, kz = blockIdx.z;
    const int tbase = blockIdx.x * 512;
    const int tid = threadIdx.x;
    const int hg = tid >> 6, h0 = hg * 8, rg = tid & 63;
    const int r0 = rg * 4;
    const int keyc = rg & 7;

    {
        const float4* src = (const float4*)(g_p2 + (b * 512 + kz * 64) * NH);
#pragma unroll
        for (int it = 0; it < 4; it++) {
            int i = tid + 128 * it;
            cpa16(p2_base + i * 16, src + i);
        }
        const float* base = F + (b * NT + tbase) * NF + kz * 128;
#pragma unroll
        for (int it = 0; it < 16; it++) {
            int i = tid + 128 * it;
            int row = i >> 3, c = i & 7;
            cpa16(fs_base + (row * 8 + (c ^ ((row >> 2) & 7))) * 16,
                  base + row * NF + c * 4);
        }
        cpacommit();
    }

    ull acc[4][8];
#pragma unroll
    for (int r = 0; r < 4; r++)
#pragma unroll
        for (int hh = 0; hh < 8; hh++) acc[r][hh] = 0ull;

    for (int s = 0; s < 8; s++) {
        cpawait0();
        __syncthreads();
        if (s < 7) {
            int sn = s + 1;
            int half = sn >> 2, kc = sn & 3;
            const float* base = F + (b * NT + tbase + half * 256) * NF
                              + kz * 128 + kc * 32;
            unsigned dstb = fs_base + (sn & 1) * 2048 * 16;
#pragma unroll
            for (int it = 0; it < 16; it++) {
                int i = tid + 128 * it;
                int row = i >> 3, c = i & 7;
                cpa16(dstb + (row * 8 + (c ^ ((row >> 2) & 7))) * 16,
                      base + row * NF + c * 4);
            }
            cpacommit();
        }
        const float4* buf = Fs + (s & 1) * 2048;
        const int kc = s & 3;
#pragma unroll
        for (int c = 0; c < 8; c++) {
            ull pp0[8], pp1[8];
            {
                const ulonglong2* q0 = (const ulonglong2*)(p2s + (kc * 16 + c * 2) * NH + h0);
                const ulonglong2* q1 = (const ulonglong2*)(p2s + (kc * 16 + c * 2 + 1) * NH + h0);
#pragma unroll
                for (int q = 0; q < 4; q++) {
                    ulonglong2 a = q0[q]; pp0[2 * q] = a.x; pp0[2 * q + 1] = a.y;
                    ulonglong2 bq = q1[q]; pp1[2 * q] = bq.x; pp1[2 * q + 1] = bq.y;
                }
            }
#pragma unroll
            for (int r = 0; r < 4; r++) {
                int row = r0 + r;
                ulonglong2 u = *(const ulonglong2*)(buf + row * 8 + (c ^ keyc));
#pragma unroll
                for (int hh = 0; hh < 8; hh++) {
                    acc[r][hh] = ffma2(u.x, pp0[hh], acc[r][hh]);
                    acc[r][hh] = ffma2(u.y, pp1[hh], acc[r][hh]);
                }
            }
        }
        if (kc == 3) {
            int half = s >> 2;
#pragma unroll
            for (int hh = 0; hh < 8; hh++) {
                float4 o;
                float lo, hi;
                upk2(acc[0][hh], lo, hi); o.x = lo + hi;
                upk2(acc[1][hh], lo, hi); o.y = lo + hi;
                upk2(acc[2][hh], lo, hi); o.z = lo + hi;
                upk2(acc[3][hh], lo, hi); o.w = lo + hi;
                *(float4*)(g_Lp + ((kz * NB + b) * NH + h0 + hh) * NT
                           + tbase + half * 256 + r0) = o;
            }
#pragma unroll
            for (int r = 0; r < 4; r++)
#pragma unroll
                for (int hh = 0; hh < 8; hh++) acc[r][hh] = 0ull;
        }
    }
}

// ---------------- softmax: sum 8 k-split partials, softmax, write g_attn
__global__ void softmax_kernel() {
    __shared__ float red[8];
    const int bh = blockIdx.x, tid = threadIdx.x;
    const int wid = tid >> 5, lid = tid & 31;
    const float4* L0 = (const float4*)(g_Lp + bh * NT);
    const int STRIDE4 = NB * NH * NT / 4;
    float4* Ao = (float4*)(g_attn + bh * NT);

    float4 v[4];
    float lmax = -1e30f;
#pragma unroll
    for (int j = 0; j < 4; j++) {
        int i = tid + 256 * j;
        float4 x = L0[i];
#pragma unroll
        for (int k = 1; k < KS; k++) {
            float4 a = L0[k * STRIDE4 + i];
            x.x += a.x; x.y += a.y; x.z += a.z; x.w += a.w;
        }
        v[j] = x;
        lmax = fmaxf(lmax, fmaxf(fmaxf(x.x, x.y), fmaxf(x.z, x.w)));
    }
#pragma unroll
    for (int o = 16; o > 0; o >>= 1)
        lmax = fmaxf(lmax, __shfl_xor_sync(0xffffffffu, lmax, o));
    if (lid == 0) red[wid] = lmax;
    __syncthreads();
    {
        float t = red[lid & 7];
#pragma unroll
        for (int o = 4; o > 0; o >>= 1)
            t = fmaxf(t, __shfl_xor_sync(0xffffffffu, t, o));
        lmax = t;
    }
    float lsum = 0.f;
#pragma unroll
    for (int j = 0; j < 4; j++) {
        float4 x = v[j];
        x.x = __expf(x.x - lmax); x.y = __expf(x.y - lmax);
        x.z = __expf(x.z - lmax); x.w = __expf(x.w - lmax);
        v[j] = x;
        lsum += x.x + x.y + x.z + x.w;
    }
#pragma unroll
    for (int o = 16; o > 0; o >>= 1)
        lsum += __shfl_xor_sync(0xffffffffu, lsum, o);
    __syncthreads();
    if (lid == 0) red[wid] = lsum;
    __syncthreads();
    {
        float t = red[lid & 7];
#pragma unroll
        for (int o = 4; o > 0; o >>= 1)
            t += __shfl_xor_sync(0xffffffffu, t, o);
        lsum = t;
    }
    float inv = 1.f / lsum;
#pragma unroll
    for (int j = 0; j < 4; j++) {
        float4 x = v[j];
        x.x *= inv; x.y *= inv; x.z *= inv; x.w *= inv;
        Ao[tid + 256 * j] = x;
    }
}

// ---------------- pass2: wp[b][c][h][f] = sum_{t in 256-chunk} A[h][t]*F[t][f]
// grid (16 t-chunks, 32 b reversed), 256 threads, 2 blocks/SM; 32 stages of 8 rows
__global__ __launch_bounds__(256, 2) void pass2_kernel(const float* __restrict__ F) {
    extern __shared__ __align__(16) char sm2[];
    float4* Fs = (float4*)sm2;                        // 2 * 2048 float4 = 64 KB
    ull* attnP = (ull*)(sm2 + 2 * 2048 * 16);         // 256 * APS ull = 36 KB
    const unsigned fs_base = (unsigned)__cvta_generic_to_shared(Fs);

    const int b = (NB - 1) - blockIdx.y;
    const int cblk = blockIdx.x;
    const int tb = cblk * 256;
    const int tid = threadIdx.x;
    const int hg = tid >> 7, h0 = hg * 8, fg = tid & 127;

    {
        const float* base = F + (b * NT + tb) * NF;
#pragma unroll
        for (int it = 0; it < 8; it++) {
            int i = tid + 256 * it;
            int row = i >> 8, c = i & 255;
            cpa16(fs_base + (row * 256 + c) * 16, base + row * NF + c * 4);
        }
        cpacommit();
        // attn pair table (256 t rows): coalesced LDG, pk2, padded STS
#pragma unroll
        for (int it = 0; it < 16; it++) {
            int i = tid + 256 * it;                   // 0..4095
            int h = i >> 8, t = i & 255;
            float a = g_attn[(b * NH + h) * NT + tb + t];
            attnP[t * APS + h] = pk2(a, a);
        }
    }

    ull acc[8][4];
#pragma unroll
    for (int hh = 0; hh < 8; hh++)
#pragma unroll
        for (int r = 0; r < 4; r++) acc[hh][r] = 0ull;

    for (int s = 0; s < 32; s++) {
        cpawait0();
        __syncthreads();
        if (s < 31) {
            int t0 = tb + (s + 1) * 8;
            const float* base = F + (b * NT + t0) * NF;
            unsigned dstb = fs_base + ((s + 1) & 1) * 2048 * 16;
#pragma unroll
            for (int it = 0; it < 8; it++) {
                int i = tid + 256 * it;
                int row = i >> 8, c = i & 255;
                cpa16(dstb + (row * 256 + c) * 16, base + row * NF + c * 4);
            }
            cpacommit();
        }
        const float4* buf = Fs + (s & 1) * 2048;
#pragma unroll
        for (int kk = 0; kk < 8; kk++) {
            ull pp[8];
            {
                const ulonglong2* q =
                    (const ulonglong2*)(attnP + (s * 8 + kk) * APS + h0);
#pragma unroll
                for (int qi = 0; qi < 4; qi++) {
                    ulonglong2 a = q[qi];
                    pp[2 * qi] = a.x; pp[2 * qi + 1] = a.y;
                }
            }
            ulonglong2 ua = *(const ulonglong2*)(buf + kk * 256 + fg);
            ulonglong2 ub = *(const ulonglong2*)(buf + kk * 256 + 128 + fg);
#pragma unroll
            for (int hh = 0; hh < 8; hh++) {
                acc[hh][0] = ffma2(ua.x, pp[hh], acc[hh][0]);
                acc[hh][1] = ffma2(ua.y, pp[hh], acc[hh][1]);
                acc[hh][2] = ffma2(ub.x, pp[hh], acc[hh][2]);
                acc[hh][3] = ffma2(ub.y, pp[hh], acc[hh][3]);
            }
        }
    }
#pragma unroll
    for (int hh = 0; hh < 8; hh++) {
        float o0, o1, o2, o3;
        float* wpp = g_wp + ((b * TC2 + cblk) * NH + h0 + hh) * NF;
        upk2(acc[hh][0], o0, o1); upk2(acc[hh][1], o2, o3);
        *(float4*)(wpp + fg * 4) = make_float4(o0, o1, o2, o3);
        upk2(acc[hh][2], o0, o1); upk2(acc[hh][3], o2, o3);
        *(float4*)(wpp + 512 + fg * 4) = make_float4(o0, o1, o2, o3);
    }
}

// op[fc][b][j] = sum_{f in 64-chunk fc} (sum_c wp[b][c][..][f]) * Wv[f][j]
__global__ void outpart_kernel(const float* __restrict__ Wv) {
    __shared__ float ws[16][2][64];
    const int jt = blockIdx.x, fc = blockIdx.y, bg = blockIdx.z;
    const int tid = threadIdx.x;
    for (int i = tid; i < 16 * 2 * 64; i += 128) {
        int bb = i >> 7, hl = (i >> 6) & 1, fl = i & 63;
        int bglob = bg * 16 + bb;
        float s = 0.f;
#pragma unroll
        for (int c = 0; c < TC2; c++)
            s += g_wp[((bglob * TC2 + c) * NH + jt * 2 + hl) * NF + fc * 64 + fl];
        ws[bb][hl][fl] = s;
    }
    __syncthreads();
    const int j = jt * 128 + tid;
    const int hl = tid >> 6;
    float acc[16];
#pragma unroll
    for (int bb = 0; bb < 16; bb++) acc[bb] = 0.f;
    for (int fl = 0; fl < 64; fl++) {
        float wvv = Wv[(fc * 64 + fl) * NDM + j];
#pragma unroll
        for (int bb = 0; bb < 16; bb++) acc[bb] += ws[bb][hl][fl] * wvv;
    }
#pragma unroll
    for (int bb = 0; bb < 16; bb++)
        g_op[(fc * 32 + bg * 16 + bb) * NDM + j] = acc[bb];
}

// ---------------- host launcher ----------------
extern "C" void kernel_launch(void* const* d_in, const int* in_sizes, int n_in,
                              void* d_out, int out_size) {
    const float* features = (const float*)d_in[0];
    const float* state    = (const float*)d_in[1];
    const float* Wq       = (const float*)d_in[2];
    const float* bq       = (const float*)d_in[3];
    const float* Wv       = (const float*)d_in[4];
    const float* bv       = (const float*)d_in[5];
    const float* Wd       = (const float*)d_in[6];
    const float* bd       = (const float*)d_in[7];
    float* out = (float*)d_out;

    void *p_qpart, *p_fpart, *p_q;
    cudaGetSymbolAddress(&p_qpart, g_qpart);
    cudaGetSymbolAddress(&p_fpart, g_fpart);
    cudaGetSymbolAddress(&p_q, g_q);

    const int SM1 = 2 * 2048 * 16 + 1024 * 8;        // 73728 -> 3 blocks/SM
    const int SM2 = 2 * 2048 * 16 + 256 * APS * 8;   // 102400 -> 2 blocks/SM
    static int cfg_done = 0;
    if (!cfg_done) {
        cudaFuncSetAttribute(pass1_kernel,
            cudaFuncAttributeMaxDynamicSharedMemorySize, SM1);
        cudaFuncSetAttribute(pass2_kernel,
            cudaFuncAttributeMaxDynamicSharedMemorySize, SM2);
        cfg_done = 1;
    }

    // q = state @ Wq + bq
    gemv_part_kernel<<<dim3(8, 32), 128>>>(state, Wq, (float*)p_qpart);
    combine32_kernel<<<128, 256>>>((const float*)p_qpart, bq, (float*)p_q);
    // p2 pairs
    pcalc_kernel<<<dim3(64, 4), 256>>>(Wv);
    // logit partials (k-split x8, 3 blocks/SM)
    pass1_kernel<<<dim3(8, 32, KS), 128, SM1>>>(features);
    // softmax -> attn [b][h][t]
    softmax_kernel<<<NB * NH, 256>>>();
    // w partials = attn @ features (16 chunks of 256 t)
    pass2_kernel<<<dim3(TC2, 32), 256, SM2>>>(features);
    // op = (sum_c wp) @ Wv   (per f-chunk partials)
    outpart_kernel<<<dim3(8, 16, 2), 128>>>(Wv);
    // final = (op-sum + bv) @ Wd + bd
    gemv_final_kernel<<<dim3(8, 32), 128>>>(Wd, bv, (float*)p_fpart);
    combine32_kernel<<<128, 256>>>((const float*)p_fpart, bd, out);
    (void)in_sizes; (void)n_in; (void)out_size;
}

// round 15
// speedup vs baseline: 1.0428x; 1.0238x over previous
#include <cuda_runtime.h>

// Problem constants
#define NB   32
#define NT   4096
#define NF   1024     // F_IN
#define NH   16
#define NDEP 64
#define NDM  1024     // D
#define KS   4        // pass1 k-split factor (256 k per split)
#define TC2  16       // pass2 t-chunks (256 t each)
#define APS  18       // attnP row stride (ull), even => ulonglong2-aligned

typedef unsigned long long ull;

// ---------------- scratch (device globals; no allocation) ----------------
__device__ float g_qpart[32 * NB * NDM];
__device__ float g_q[NB * NDM];
__device__ ull   g_p2[NB * 512 * NH];            // (p[2P][h], p[2P+1][h]) pairs
__device__ float g_Lp[KS * NB * NH * NT];        // logit k-split partials (32MB)
__device__ float g_attn[NB * NH * NT];           // attn weights [b][h][t]
__device__ float g_wp[NB * TC2 * NH * NF];       // pass2 t-chunk partials (32MB)
__device__ float g_op[16 * NB * NDM];
__device__ float g_fpart[32 * NB * NDM];

// ---------------- helpers ----------------
__device__ __forceinline__ ull pk2(float lo, float hi) {
    ull r;
    asm("mov.b64 %0, {%1, %2};" : "=l"(r) : "f"(lo), "f"(hi));
    return r;
}
__device__ __forceinline__ ull ffma2(ull a, ull b, ull c) {
    ull d;
    asm("fma.rn.f32x2 %0, %1, %2, %3;" : "=l"(d) : "l"(a), "l"(b), "l"(c));
    return d;
}
__device__ __forceinline__ void upk2(ull v, float& lo, float& hi) {
    asm("mov.b64 {%0, %1}, %2;" : "=f"(lo), "=f"(hi) : "l"(v));
}
__device__ __forceinline__ void cpa16(unsigned dst, const void* src) {
    asm volatile("cp.async.cg.shared.global [%0], [%1], 16;" :: "r"(dst), "l"(src));
}
__device__ __forceinline__ void cpacommit() {
    asm volatile("cp.async.commit_group;" ::: "memory");
}
__device__ __forceinline__ void cpawait0() {
    asm volatile("cp.async.wait_group 0;" ::: "memory");
}

// ---------------- 32-batch GEMV, 32-way k-split partials ----------
__global__ void gemv_part_kernel(const float* __restrict__ X,
                                 const float* __restrict__ W,
                                 float* __restrict__ part) {
    __shared__ float xs[32][32];
    const int jt = blockIdx.x, kc = blockIdx.y, tid = threadIdx.x;
    for (int i = tid; i < 32 * 32; i += 128) {
        int bb = i >> 5, kl = i & 31;
        xs[bb][kl] = X[bb * NDM + kc * 32 + kl];
    }
    __syncthreads();
    const int j = jt * 128 + tid;
    float acc[32];
#pragma unroll
    for (int bb = 0; bb < 32; bb++) acc[bb] = 0.f;
    for (int kl = 0; kl < 32; kl++) {
        float wv = W[(kc * 32 + kl) * NDM + j];
#pragma unroll
        for (int bb = 0; bb < 32; bb++) acc[bb] += xs[bb][kl] * wv;
    }
#pragma unroll
    for (int bb = 0; bb < 32; bb++) part[(kc * 32 + bb) * NDM + j] = acc[bb];
}

// final GEMV: X built inline as bv + sum_fc op[fc]
__global__ void gemv_final_kernel(const float* __restrict__ W,
                                  const float* __restrict__ bv,
                                  float* __restrict__ part) {
    __shared__ float xs[32][32];
    const int jt = blockIdx.x, kc = blockIdx.y, tid = threadIdx.x;
    for (int i = tid; i < 32 * 32; i += 128) {
        int bb = i >> 5, kl = i & 31;
        int col = kc * 32 + kl;
        float s = bv[col];
#pragma unroll
        for (int fc = 0; fc < 16; fc++)
            s += g_op[fc * (32 * NDM) + bb * NDM + col];
        xs[bb][kl] = s;
    }
    __syncthreads();
    const int j = jt * 128 + tid;
    float acc[32];
#pragma unroll
    for (int bb = 0; bb < 32; bb++) acc[bb] = 0.f;
    for (int kl = 0; kl < 32; kl++) {
        float wv = W[(kc * 32 + kl) * NDM + j];
#pragma unroll
        for (int bb = 0; bb < 32; bb++) acc[bb] += xs[bb][kl] * wv;
    }
#pragma unroll
    for (int bb = 0; bb < 32; bb++) part[(kc * 32 + bb) * NDM + j] = acc[bb];
}

__global__ void combine32_kernel(const float* __restrict__ part,
                                 const float* __restrict__ bias,
                                 float* __restrict__ out) {
    int i = blockIdx.x * 256 + threadIdx.x;
    float s = bias[i & (NDM - 1)];
#pragma unroll
    for (int c = 0; c < 32; c++) s += part[c * (32 * NDM) + i];
    out[i] = s;
}

// ---------------- p2[b][P][h] = (1/8)*(sum_d Wv[2P][..]q, sum_d Wv[2P+1][..]q)
__global__ void pcalc_kernel(const float* __restrict__ Wv) {
    __shared__ float qs[8][NDM];
    const int ft = blockIdx.x, bg = blockIdx.y, tid = threadIdx.x;
    for (int i = tid; i < 8 * NDM; i += 256)
        qs[i >> 10][i & 1023] = g_q[(bg * 8 + (i >> 10)) * NDM + (i & 1023)];
    __syncthreads();
    const int h = tid >> 4, fl = tid & 15;
    const int f = ft * 16 + fl;
    float acc[8];
#pragma unroll
    for (int bb = 0; bb < 8; bb++) acc[bb] = 0.f;
    for (int d = 0; d < NDEP; d++) {
        float wv = Wv[f * NDM + h * NDEP + d];
#pragma unroll
        for (int bb = 0; bb < 8; bb++) acc[bb] += wv * qs[bb][h * NDEP + d];
    }
    float* p2f = (float*)g_p2;
#pragma unroll
    for (int bb = 0; bb < 8; bb++) {
        int b = bg * 8 + bb;
        p2f[(((b * 512) + (f >> 1)) * NH + h) * 2 + (f & 1)] = acc[bb] * 0.125f;
    }
}

// ---------------- pass1: Lp[kz][b][h][t] = sum_{k in 256-slice kz} F[t][k]*p[k][h]
// grid (8 t-tiles of 512, 32 b, 4 kz), 128 threads; p2 staged per-kc (2KB x2)
// smem 64KB Fs + 4KB p2 stages = 68KB -> 3 blocks/SM
__global__ __launch_bounds__(128, 3) void pass1_kernel(const float* __restrict__ F) {
    extern __shared__ __align__(16) char sm1[];
    float4* Fs = (float4*)sm1;                        // 2 * 2048 float4 = 64KB
    ull* p2s = (ull*)(sm1 + 2 * 2048 * 16);           // 2 * 256 ull = 4KB
    const unsigned fs_base = (unsigned)__cvta_generic_to_shared(Fs);
    const unsigned p2_base = (unsigned)__cvta_generic_to_shared(p2s);

    const int b = blockIdx.y, kz = blockIdx.z;
    const int tbase = blockIdx.x * 512;
    const int tid = threadIdx.x;
    const int hg = tid >> 6, h0 = hg * 8, rg = tid & 63;
    const int r0 = rg * 4;
    const int keyc = rg & 7;

    {
        // p2 stage 0 (kc=0): pairs kz*128 .. +16, 2KB = 128 float4
        const float4* psrc = (const float4*)(g_p2 + (b * 512 + kz * 128) * NH);
        cpa16(p2_base + tid * 16, psrc + tid);
        const float* base = F + (b * NT + tbase) * NF + kz * 256;
#pragma unroll
        for (int it = 0; it < 16; it++) {
            int i = tid + 128 * it;
            int row = i >> 3, c = i & 7;
            cpa16(fs_base + (row * 8 + (c ^ ((row >> 2) & 7))) * 16,
                  base + row * NF + c * 4);
        }
        cpacommit();
    }

    ull acc[4][8];
#pragma unroll
    for (int r = 0; r < 4; r++)
#pragma unroll
        for (int hh = 0; hh < 8; hh++) acc[r][hh] = 0ull;

    for (int s = 0; s < 16; s++) {
        cpawait0();
        __syncthreads();
        if (s < 15) {
            int sn = s + 1;
            int half = sn >> 3, kcn = sn & 7;
            const float* base = F + (b * NT + tbase + half * 256) * NF
                              + kz * 256 + kcn * 32;
            unsigned dstb = fs_base + (sn & 1) * 2048 * 16;
#pragma unroll
            for (int it = 0; it < 16; it++) {
                int i = tid + 128 * it;
                int row = i >> 3, c = i & 7;
                cpa16(dstb + (row * 8 + (c ^ ((row >> 2) & 7))) * 16,
                      base + row * NF + c * 4);
            }
            // p2 stage for kcn: 16 pairs x 16 h = 2KB
            const float4* psrc =
                (const float4*)(g_p2 + (b * 512 + kz * 128 + kcn * 16) * NH);
            cpa16(p2_base + (sn & 1) * 2048 + tid * 16, psrc + tid);
            cpacommit();
        }
        const float4* buf = Fs + (s & 1) * 2048;
        const ull* pbuf = p2s + (s & 1) * 256;
        const int kc = s & 7;
#pragma unroll
        for (int c = 0; c < 8; c++) {
            ull pp0[8], pp1[8];
            {
                const ulonglong2* q0 = (const ulonglong2*)(pbuf + (c * 2) * NH + h0);
                const ulonglong2* q1 = (const ulonglong2*)(pbuf + (c * 2 + 1) * NH + h0);
#pragma unroll
                for (int q = 0; q < 4; q++) {
                    ulonglong2 a = q0[q]; pp0[2 * q] = a.x; pp0[2 * q + 1] = a.y;
                    ulonglong2 bq = q1[q]; pp1[2 * q] = bq.x; pp1[2 * q + 1] = bq.y;
                }
            }
#pragma unroll
            for (int r = 0; r < 4; r++) {
                int row = r0 + r;
                ulonglong2 u = *(const ulonglong2*)(buf + row * 8 + (c ^ keyc));
#pragma unroll
                for (int hh = 0; hh < 8; hh++) {
                    acc[r][hh] = ffma2(u.x, pp0[hh], acc[r][hh]);
                    acc[r][hh] = ffma2(u.y, pp1[hh], acc[r][hh]);
                }
            }
        }
        if (kc == 7) {
            int half = s >> 3;
#pragma unroll
            for (int hh = 0; hh < 8; hh++) {
                float4 o;
                float lo, hi;
                upk2(acc[0][hh], lo, hi); o.x = lo + hi;
                upk2(acc[1][hh], lo, hi); o.y = lo + hi;
                upk2(acc[2][hh], lo, hi); o.z = lo + hi;
                upk2(acc[3][hh], lo, hi); o.w = lo + hi;
                *(float4*)(g_Lp + ((kz * NB + b) * NH + h0 + hh) * NT
                           + tbase + half * 256 + r0) = o;
            }
#pragma unroll
            for (int r = 0; r < 4; r++)
#pragma unroll
                for (int hh = 0; hh < 8; hh++) acc[r][hh] = 0ull;
        }
    }
}

// ---------------- softmax: sum 4 k-split partials, softmax, write g_attn
__global__ void softmax_kernel() {
    __shared__ float red[8];
    const int bh = blockIdx.x, tid = threadIdx.x;
    const int wid = tid >> 5, lid = tid & 31;
    const float4* L0 = (const float4*)(g_Lp + bh * NT);
    const int STRIDE4 = NB * NH * NT / 4;
    float4* Ao = (float4*)(g_attn + bh * NT);

    float4 v[4];
    float lmax = -1e30f;
#pragma unroll
    for (int j = 0; j < 4; j++) {
        int i = tid + 256 * j;
        float4 x = L0[i];
#pragma unroll
        for (int k = 1; k < KS; k++) {
            float4 a = L0[k * STRIDE4 + i];
            x.x += a.x; x.y += a.y; x.z += a.z; x.w += a.w;
        }
        v[j] = x;
        lmax = fmaxf(lmax, fmaxf(fmaxf(x.x, x.y), fmaxf(x.z, x.w)));
    }
#pragma unroll
    for (int o = 16; o > 0; o >>= 1)
        lmax = fmaxf(lmax, __shfl_xor_sync(0xffffffffu, lmax, o));
    if (lid == 0) red[wid] = lmax;
    __syncthreads();
    {
        float t = red[lid & 7];
#pragma unroll
        for (int o = 4; o > 0; o >>= 1)
            t = fmaxf(t, __shfl_xor_sync(0xffffffffu, t, o));
        lmax = t;
    }
    float lsum = 0.f;
#pragma unroll
    for (int j = 0; j < 4; j++) {
        float4 x = v[j];
        x.x = __expf(x.x - lmax); x.y = __expf(x.y - lmax);
        x.z = __expf(x.z - lmax); x.w = __expf(x.w - lmax);
        v[j] = x;
        lsum += x.x + x.y + x.z + x.w;
    }
#pragma unroll
    for (int o = 16; o > 0; o >>= 1)
        lsum += __shfl_xor_sync(0xffffffffu, lsum, o);
    __syncthreads();
    if (lid == 0) red[wid] = lsum;
    __syncthreads();
    {
        float t = red[lid & 7];
#pragma unroll
        for (int o = 4; o > 0; o >>= 1)
            t += __shfl_xor_sync(0xffffffffu, t, o);
        lsum = t;
    }
    float inv = 1.f / lsum;
#pragma unroll
    for (int j = 0; j < 4; j++) {
        float4 x = v[j];
        x.x *= inv; x.y *= inv; x.z *= inv; x.w *= inv;
        Ao[tid + 256 * j] = x;
    }
}

// ---------------- pass2: wp[b][c][h][f] = sum_{t in 256-chunk} A[h][t]*F[t][f]
// grid (16 t-chunks, 32 b reversed), 256 threads, 2 blocks/SM; 32 stages of 8 rows
__global__ __launch_bounds__(256, 2) void pass2_kernel(const float* __restrict__ F) {
    extern __shared__ __align__(16) char sm2[];
    float4* Fs = (float4*)sm2;                        // 2 * 2048 float4 = 64 KB
    ull* attnP = (ull*)(sm2 + 2 * 2048 * 16);         // 256 * APS ull = 36 KB
    const unsigned fs_base = (unsigned)__cvta_generic_to_shared(Fs);

    const int b = (NB - 1) - blockIdx.y;
    const int cblk = blockIdx.x;
    const int tb = cblk * 256;
    const int tid = threadIdx.x;
    const int hg = tid >> 7, h0 = hg * 8, fg = tid & 127;

    {
        const float* base = F + (b * NT + tb) * NF;
#pragma unroll
        for (int it = 0; it < 8; it++) {
            int i = tid + 256 * it;
            int row = i >> 8, c = i & 255;
            cpa16(fs_base + (row * 256 + c) * 16, base + row * NF + c * 4);
        }
        cpacommit();
        // attn pair table (256 t rows): coalesced LDG, pk2, padded STS
#pragma unroll
        for (int it = 0; it < 16; it++) {
            int i = tid + 256 * it;                   // 0..4095
            int h = i >> 8, t = i & 255;
            float a = g_attn[(b * NH + h) * NT + tb + t];
            attnP[t * APS + h] = pk2(a, a);
        }
    }

    ull acc[8][4];
#pragma unroll
    for (int hh = 0; hh < 8; hh++)
#pragma unroll
        for (int r = 0; r < 4; r++) acc[hh][r] = 0ull;

    for (int s = 0; s < 32; s++) {
        cpawait0();
        __syncthreads();
        if (s < 31) {
            int t0 = tb + (s + 1) * 8;
            const float* base = F + (b * NT + t0) * NF;
            unsigned dstb = fs_base + ((s + 1) & 1) * 2048 * 16;
#pragma unroll
            for (int it = 0; it < 8; it++) {
                int i = tid + 256 * it;
                int row = i >> 8, c = i & 255;
                cpa16(dstb + (row * 256 + c) * 16, base + row * NF + c * 4);
            }
            cpacommit();
        }
        const float4* buf = Fs + (s & 1) * 2048;
#pragma unroll
        for (int kk = 0; kk < 8; kk++) {
            ull pp[8];
            {
                const ulonglong2* q =
                    (const ulonglong2*)(attnP + (s * 8 + kk) * APS + h0);
#pragma unroll
                for (int qi = 0; qi < 4; qi++) {
                    ulonglong2 a = q[qi];
                    pp[2 * qi] = a.x; pp[2 * qi + 1] = a.y;
                }
            }
            ulonglong2 ua = *(const ulonglong2*)(buf + kk * 256 + fg);
            ulonglong2 ub = *(const ulonglong2*)(buf + kk * 256 + 128 + fg);
#pragma unroll
            for (int hh = 0; hh < 8; hh++) {
                acc[hh][0] = ffma2(ua.x, pp[hh], acc[hh][0]);
                acc[hh][1] = ffma2(ua.y, pp[hh], acc[hh][1]);
                acc[hh][2] = ffma2(ub.x, pp[hh], acc[hh][2]);
                acc[hh][3] = ffma2(ub.y, pp[hh], acc[hh][3]);
            }
        }
    }
#pragma unroll
    for (int hh = 0; hh < 8; hh++) {
        float o0, o1, o2, o3;
        float* wpp = g_wp + ((b * TC2 + cblk) * NH + h0 + hh) * NF;
        upk2(acc[hh][0], o0, o1); upk2(acc[hh][1], o2, o3);
        *(float4*)(wpp + fg * 4) = make_float4(o0, o1, o2, o3);
        upk2(acc[hh][2], o0, o1); upk2(acc[hh][3], o2, o3);
        *(float4*)(wpp + 512 + fg * 4) = make_float4(o0, o1, o2, o3);
    }
}

// op[fc][b][j] = sum_{f in 64-chunk fc} (sum_c wp[b][c][..][f]) * Wv[f][j]
__global__ void outpart_kernel(const float* __restrict__ Wv) {
    __shared__ float ws[16][2][64];
    const int jt = blockIdx.x, fc = blockIdx.y, bg = blockIdx.z;
    const int tid = threadIdx.x;
    for (int i = tid; i < 16 * 2 * 64; i += 128) {
        int bb = i >> 7, hl = (i >> 6) & 1, fl = i & 63;
        int bglob = bg * 16 + bb;
        float s = 0.f;
#pragma unroll
        for (int c = 0; c < TC2; c++)
            s += g_wp[((bglob * TC2 + c) * NH + jt * 2 + hl) * NF + fc * 64 + fl];
        ws[bb][hl][fl] = s;
    }
    __syncthreads();
    const int j = jt * 128 + tid;
    const int hl = tid >> 6;
    float acc[16];
#pragma unroll
    for (int bb = 0; bb < 16; bb++) acc[bb] = 0.f;
    for (int fl = 0; fl < 64; fl++) {
        float wvv = Wv[(fc * 64 + fl) * NDM + j];
#pragma unroll
        for (int bb = 0; bb < 16; bb++) acc[bb] += ws[bb][hl][fl] * wvv;
    }
#pragma unroll
    for (int bb = 0; bb < 16; bb++)
        g_op[(fc * 32 + bg * 16 + bb) * NDM + j] = acc[bb];
}

// ---------------- host launcher ----------------
extern "C" void kernel_launch(void* const* d_in, const int* in_sizes, int n_in,
                              void* d_out, int out_size) {
    const float* features = (const float*)d_in[0];
    const float* state    = (const float*)d_in[1];
    const float* Wq       = (const float*)d_in[2];
    const float* bq       = (const float*)d_in[3];
    const float* Wv       = (const float*)d_in[4];
    const float* bv       = (const float*)d_in[5];
    const float* Wd       = (const float*)d_in[6];
    const float* bd       = (const float*)d_in[7];
    float* out = (float*)d_out;

    void *p_qpart, *p_fpart, *p_q;
    cudaGetSymbolAddress(&p_qpart, g_qpart);
    cudaGetSymbolAddress(&p_fpart, g_fpart);
    cudaGetSymbolAddress(&p_q, g_q);

    const int SM1 = 2 * 2048 * 16 + 2 * 256 * 8;     // 69632 -> 3 blocks/SM
    const int SM2 = 2 * 2048 * 16 + 256 * APS * 8;   // 102400 -> 2 blocks/SM
    static int cfg_done = 0;
    if (!cfg_done) {
        cudaFuncSetAttribute(pass1_kernel,
            cudaFuncAttributeMaxDynamicSharedMemorySize, SM1);
        cudaFuncSetAttribute(pass2_kernel,
            cudaFuncAttributeMaxDynamicSharedMemorySize, SM2);
        cfg_done = 1;
    }

    // q = state @ Wq + bq
    gemv_part_kernel<<<dim3(8, 32), 128>>>(state, Wq, (float*)p_qpart);
    combine32_kernel<<<128, 256>>>((const float*)p_qpart, bq, (float*)p_q);
    // p2 pairs
    pcalc_kernel<<<dim3(64, 4), 256>>>(Wv);
    // logit partials (k-split x4, staged p2, 3 blocks/SM)
    pass1_kernel<<<dim3(8, 32, KS), 128, SM1>>>(features);
    // softmax -> attn [b][h][t]
    softmax_kernel<<<NB * NH, 256>>>();
    // w partials = attn @ features (16 chunks of 256 t)
    pass2_kernel<<<dim3(TC2, 32), 256, SM2>>>(features);
    // op = (sum_c wp) @ Wv   (per f-chunk partials)
    outpart_kernel<<<dim3(8, 16, 2), 128>>>(Wv);
    // final = (op-sum + bv) @ Wd + bd
    gemv_final_kernel<<<dim3(8, 32), 128>>>(Wd, bv, (float*)p_fpart);
    combine32_kernel<<<128, 256>>>((const float*)p_fpart, bd, out);
    (void)in_sizes; (void)n_in; (void)out_size;
}